// round 4
// baseline (speedup 1.0000x reference)
#include <cuda_runtime.h>
#include <math.h>
#include <stdint.h>

// ---------------------------------------------------------------------------
// QuantSoftmax: B=32, C=128, H=W=80 (HW=6400). int32 input (int8 repr, zp=0),
// float32 output. Piecewise-quantized exp (qint16) + reciprocal (qint16),
// requantized to int8*OUT_SCALE.
//
// xd = -(qmax - q)*ds takes only 256 values -> exp collapses to a 256-entry
// LUT built once per launch (depends on data_scale). Channel data is staged
// in shared memory BYTE-packed (4 channels / u32, 16 KB/CTA) to maximize
// occupancy; pass 3 re-looks-up the exp LUT instead of caching exp_q.
// ---------------------------------------------------------------------------

#define C_DIM 128
#define HW_DIM 6400
#define NTHREADS 128   // pixels per block
#define KROWS 32       // 128 channels / 4 per u32

__device__ float g_exp_lut[256];   // quantized exp value (integer-valued float)
__device__ float g_rtab1[256];     // recip table, region (0.1, 250)
__device__ float g_rtab2[256];     // recip table, region (250, 500)

__device__ __forceinline__ float quant_i16(float y, float scale) {
    float q = rintf(__fdiv_rn(y, scale));           // jnp.round = half-even
    return fminf(fmaxf(q, -32768.0f), 32767.0f);
}

__device__ __forceinline__ float exp_f32(float x) {
    return (float)exp((double)x);                   // ~correctly-rounded f32 exp
}

// one block, 256 threads: build LUTs
__global__ void build_luts_kernel(const float* __restrict__ ds_ptr) {
    int i = threadIdx.x;                            // 0..255
    float ds = ds_ptr[0];
    const float ESCALE = (float)(2.0 / 65535.0);
    const float RSCALE = (float)((1.0 / 0.1) * 2.0 / 65535.0);

    // ---- exp LUT over d = qmax - q in [0,255], x = -d*ds ----
    float x = __fmul_rn(-(float)i, ds);
    // left constant: quant(exp(-40))
    float y = quant_i16(exp_f32(-40.0f), ESCALE);
    // region (-40,-20) line
    if (x >= -40.0f) {
        float y0 = exp_f32(-40.0f), y1 = exp_f32(-20.0f);
        float t = __fadd_rn(y0, __fmul_rn(__fadd_rn(x, 40.0f),
                                          __fdiv_rn(__fadd_rn(y1, -y0), 20.0f)));
        y = quant_i16(t, ESCALE);
    }
    // region (-20,-10) table
    if (x >= -20.0f) {
        float idxf = rintf(__fmul_rn(__fadd_rn(x, 20.0f), (float)(255.0 / 10.0)));
        idxf = fminf(fmaxf(idxf, 0.0f), 255.0f);
        float step = __fdiv_rn(10.0f, 255.0f);
        float xs = __fadd_rn(-20.0f, __fmul_rn(idxf, step));
        y = quant_i16(exp_f32(xs), ESCALE);
    }
    // region (-10,0) table
    if (x >= -10.0f) {
        float idxf = rintf(__fmul_rn(__fadd_rn(x, 10.0f), (float)(255.0 / 10.0)));
        idxf = fminf(fmaxf(idxf, 0.0f), 255.0f);
        float step = __fdiv_rn(10.0f, 255.0f);
        float xs = __fadd_rn(-10.0f, __fmul_rn(idxf, step));
        y = quant_i16(exp_f32(xs), ESCALE);
    }
    // region (0,1) line  (only d=0 reaches x==0)
    if (x >= 0.0f) {
        float y0 = exp_f32(0.0f), y1 = exp_f32(1.0f);
        float t = __fadd_rn(y0, __fmul_rn(x, __fdiv_rn(__fadd_rn(y1, -y0), 1.0f)));
        y = quant_i16(t, ESCALE);
    }
    if (x > 1.0f) y = quant_i16(exp_f32(1.0f), ESCALE);
    g_exp_lut[i] = y;

    // ---- recip tables (independent of ds) ----
    {
        float step1 = __fdiv_rn((float)(250.0 - 0.1), 255.0f);
        float xs1 = __fadd_rn(0.1f, __fmul_rn((float)i, step1));
        g_rtab1[i] = quant_i16(__fdiv_rn(1.0f, xs1), RSCALE);
        float step2 = __fdiv_rn(250.0f, 255.0f);
        float xs2 = __fadd_rn(250.0f, __fmul_rn((float)i, step2));
        g_rtab2[i] = quant_i16(__fdiv_rn(1.0f, xs2), RSCALE);
    }
}

__global__ __launch_bounds__(NTHREADS, 12)
void quant_softmax_kernel(const int* __restrict__ in, float* __restrict__ out) {
    // 128 channels * 128 pixels * 1B = 16 KB (byte-packed q values)
    __shared__ uint32_t sh[KROWS * NTHREADS];
    __shared__ float slut[256];

    int tid = threadIdx.x;
    slut[tid] = g_exp_lut[tid];
    slut[tid + 128] = g_exp_lut[tid + 128];
    __syncthreads();

    int tile = blockIdx.x;                 // b * 50 + tile_in_batch
    int b = tile / (HW_DIM / NTHREADS);
    int hw = (tile % (HW_DIM / NTHREADS)) * NTHREADS + tid;

    const int* p = in + (size_t)b * C_DIM * HW_DIM + hw;

    // ---- pass 1: load, byte-pack 4 channels per u32, vectorized max ----
    unsigned mx4 = 0x80808080u;            // all lanes = -128
#pragma unroll 8
    for (int k = 0; k < KROWS; k++) {
        int q0 = p[(4 * k + 0) * HW_DIM];
        int q1 = p[(4 * k + 1) * HW_DIM];
        int q2 = p[(4 * k + 2) * HW_DIM];
        int q3 = p[(4 * k + 3) * HW_DIM];
        unsigned w = (unsigned)(q0 & 0xFF) | ((unsigned)(q1 & 0xFF) << 8) |
                     ((unsigned)(q2 & 0xFF) << 16) | ((unsigned)q3 << 24);
        mx4 = __vmaxs4(mx4, w);
        sh[k * NTHREADS + tid] = w;
    }
    int m = (int)(signed char)(mx4 & 0xFF);
    m = max(m, (int)(signed char)((mx4 >> 8) & 0xFF));
    m = max(m, (int)(signed char)((mx4 >> 16) & 0xFF));
    m = max(m, (int)(signed char)(mx4 >> 24));

    // ---- pass 2: exp LUT, sum (exact: 128 ints <= 32767 -> < 2^24) ----
    float sum = 0.0f;
#pragma unroll 8
    for (int k = 0; k < KROWS; k++) {
        unsigned w = sh[k * NTHREADS + tid];
        int d0 = m - (int)(signed char)(w & 0xFF);
        int d1 = m - (int)(signed char)((w >> 8) & 0xFF);
        int d2 = m - (int)(signed char)((w >> 16) & 0xFF);
        int d3 = m - (int)(signed char)(w >> 24);
        sum += (slut[d0] + slut[d1]) + (slut[d2] + slut[d3]);
    }

    // ---- reciprocal (per pixel); shift = ceil(log2(128)) = 7 ----
    float sum_sh = rintf(sum * 0.0078125f);                 // exact /128
    sum_sh = fminf(fmaxf(sum_sh, -32768.0f), 32767.0f);
    const float DIVSC = (float)(2.0 / 65535.0 * 128.0);
    float v = __fmul_rn(sum_sh, DIVSC);
    const float RSCALE = (float)((1.0 / 0.1) * 2.0 / 65535.0);

    float r = quant_i16(__fdiv_rn(1.0f, 0.001f), RSCALE);   // left const
    if (v >= 0.001f) {                                      // line (0.001,0.1)
        float y0 = __fdiv_rn(1.0f, 0.001f), y1 = __fdiv_rn(1.0f, 0.1f);
        float t = __fadd_rn(y0, __fmul_rn(__fadd_rn(v, -0.001f),
                                          __fdiv_rn(__fadd_rn(y1, -y0), (float)(0.1 - 0.001))));
        r = quant_i16(t, RSCALE);
    }
    if (v >= 0.1f) {                                        // table (0.1,250)
        float idxf = rintf(__fmul_rn(__fadd_rn(v, -0.1f), (float)(255.0 / 249.9)));
        idxf = fminf(fmaxf(idxf, 0.0f), 255.0f);
        r = g_rtab1[(int)idxf];
    }
    if (v >= 250.0f) {                                      // table (250,500)
        float idxf = rintf(__fmul_rn(__fadd_rn(v, -250.0f), (float)(255.0 / 250.0)));
        idxf = fminf(fmaxf(idxf, 0.0f), 255.0f);
        r = g_rtab2[(int)idxf];
    }
    if (v >= 500.0f) {                                      // line (500,700)
        float y0 = __fdiv_rn(1.0f, 500.0f), y1 = __fdiv_rn(1.0f, 700.0f);
        float t = __fadd_rn(y0, __fmul_rn(__fadd_rn(v, -500.0f),
                                          __fdiv_rn(__fadd_rn(y1, -y0), 200.0f)));
        r = quant_i16(t, RSCALE);
    }
    if (v > 700.0f) r = quant_i16(__fdiv_rn(1.0f, 700.0f), RSCALE);

    // ---- pass 3: out = clip(round((exp_q*recip_q)*K), i8) * OUT_SCALE ----
    const float KF = (float)((2.0 / 65535.0) * ((1.0 / 0.1) * 2.0 / 65535.0) / (2.0 / 255.0));
    const float OUTSC = (float)(2.0 / 255.0);
    float* po = out + (size_t)b * C_DIM * HW_DIM + hw;
#pragma unroll 8
    for (int k = 0; k < KROWS; k++) {
        unsigned w = sh[k * NTHREADS + tid];
        int d0 = m - (int)(signed char)(w & 0xFF);
        int d1 = m - (int)(signed char)((w >> 8) & 0xFF);
        int d2 = m - (int)(signed char)((w >> 16) & 0xFF);
        int d3 = m - (int)(signed char)(w >> 24);
        float p0 = rintf(__fmul_rn(__fmul_rn(slut[d0], r), KF));
        float p1 = rintf(__fmul_rn(__fmul_rn(slut[d1], r), KF));
        float p2 = rintf(__fmul_rn(__fmul_rn(slut[d2], r), KF));
        float p3 = rintf(__fmul_rn(__fmul_rn(slut[d3], r), KF));
        p0 = fminf(fmaxf(p0, -128.0f), 127.0f);
        p1 = fminf(fmaxf(p1, -128.0f), 127.0f);
        p2 = fminf(fmaxf(p2, -128.0f), 127.0f);
        p3 = fminf(fmaxf(p3, -128.0f), 127.0f);
        po[(4 * k + 0) * HW_DIM] = p0 * OUTSC;
        po[(4 * k + 1) * HW_DIM] = p1 * OUTSC;
        po[(4 * k + 2) * HW_DIM] = p2 * OUTSC;
        po[(4 * k + 3) * HW_DIM] = p3 * OUTSC;
    }
}

extern "C" void kernel_launch(void* const* d_in, const int* in_sizes, int n_in,
                              void* d_out, int out_size) {
    const int* data = (const int*)d_in[0];
    const float* data_scale = (const float*)d_in[1];
    float* out = (float*)d_out;

    build_luts_kernel<<<1, 256>>>(data_scale);

    int total = in_sizes[0];
    int B = total / (C_DIM * HW_DIM);
    int blocks = B * (HW_DIM / NTHREADS);
    quant_softmax_kernel<<<blocks, NTHREADS>>>(data, out);
}

// round 5
// speedup vs baseline: 1.4594x; 1.4594x over previous
#include <cuda_runtime.h>
#include <math.h>
#include <stdint.h>

// ---------------------------------------------------------------------------
// QuantSoftmax: B=32, C=128, H=W=80 (HW=6400). int32 input (int8 repr, zp=0),
// float32 output. Piecewise-quantized exp (qint16) + reciprocal (qint16),
// requantized to int8*OUT_SCALE.
//
// xd = -(qmax - q)*ds takes only 256 values -> exp collapses to a 256-entry
// LUT built once per launch. Main kernel: 64 pixels/CTA, 2 threads/pixel
// (64 channels each). One 16KB smem buffer holds byte-packed q (pass 1)
// and is overwritten in place with u16-packed exp_q (pass 2) -> exactly one
// LUT lookup per element, one DRAM pass, 18.4KB smem -> 12 CTAs/SM.
// ---------------------------------------------------------------------------

#define C_DIM 128
#define HW_DIM 6400
#define PX 64          // pixels per block
#define NTHREADS 128   // 2 threads per pixel
#define KITER 16       // 64 channels / 4 per u32

__device__ float g_exp_lut[256];   // quantized exp value (integer-valued float)
__device__ float g_rtab1[256];     // recip table, region (0.1, 250)
__device__ float g_rtab2[256];     // recip table, region (250, 500)

__device__ __forceinline__ float quant_i16(float y, float scale) {
    float q = rintf(__fdiv_rn(y, scale));           // jnp.round = half-even
    return fminf(fmaxf(q, -32768.0f), 32767.0f);
}

__device__ __forceinline__ float exp_f32(float x) {
    return (float)exp((double)x);                   // ~correctly-rounded f32 exp
}

// one block, 256 threads: build LUTs
__global__ void build_luts_kernel(const float* __restrict__ ds_ptr) {
    int i = threadIdx.x;                            // 0..255
    float ds = ds_ptr[0];
    const float ESCALE = (float)(2.0 / 65535.0);
    const float RSCALE = (float)((1.0 / 0.1) * 2.0 / 65535.0);

    // ---- exp LUT over d = qmax - q in [0,255], x = -d*ds ----
    float x = __fmul_rn(-(float)i, ds);
    float y = quant_i16(exp_f32(-40.0f), ESCALE);   // left constant
    if (x >= -40.0f) {                              // line (-40,-20)
        float y0 = exp_f32(-40.0f), y1 = exp_f32(-20.0f);
        float t = __fadd_rn(y0, __fmul_rn(__fadd_rn(x, 40.0f),
                                          __fdiv_rn(__fadd_rn(y1, -y0), 20.0f)));
        y = quant_i16(t, ESCALE);
    }
    if (x >= -20.0f) {                              // table (-20,-10)
        float idxf = rintf(__fmul_rn(__fadd_rn(x, 20.0f), (float)(255.0 / 10.0)));
        idxf = fminf(fmaxf(idxf, 0.0f), 255.0f);
        float step = __fdiv_rn(10.0f, 255.0f);
        float xs = __fadd_rn(-20.0f, __fmul_rn(idxf, step));
        y = quant_i16(exp_f32(xs), ESCALE);
    }
    if (x >= -10.0f) {                              // table (-10,0)
        float idxf = rintf(__fmul_rn(__fadd_rn(x, 10.0f), (float)(255.0 / 10.0)));
        idxf = fminf(fmaxf(idxf, 0.0f), 255.0f);
        float step = __fdiv_rn(10.0f, 255.0f);
        float xs = __fadd_rn(-10.0f, __fmul_rn(idxf, step));
        y = quant_i16(exp_f32(xs), ESCALE);
    }
    if (x >= 0.0f) {                                // line (0,1): only d=0
        float y0 = exp_f32(0.0f), y1 = exp_f32(1.0f);
        float t = __fadd_rn(y0, __fmul_rn(x, __fdiv_rn(__fadd_rn(y1, -y0), 1.0f)));
        y = quant_i16(t, ESCALE);
    }
    if (x > 1.0f) y = quant_i16(exp_f32(1.0f), ESCALE);
    g_exp_lut[i] = y;

    // ---- recip tables (independent of ds) ----
    {
        float step1 = __fdiv_rn((float)(250.0 - 0.1), 255.0f);
        float xs1 = __fadd_rn(0.1f, __fmul_rn((float)i, step1));
        g_rtab1[i] = quant_i16(__fdiv_rn(1.0f, xs1), RSCALE);
        float step2 = __fdiv_rn(250.0f, 255.0f);
        float xs2 = __fadd_rn(250.0f, __fmul_rn((float)i, step2));
        g_rtab2[i] = quant_i16(__fdiv_rn(1.0f, xs2), RSCALE);
    }
}

__global__ __launch_bounds__(NTHREADS, 12)
void quant_softmax_kernel(const int* __restrict__ in, float* __restrict__ out) {
    // In-place union buffer, 16 KB:
    //   pass 1: slot (h*32 + 2k)*64 + px  <- 4 byte-packed q values (ch 4k..4k+3 of half h)
    //   pass 2: slots (h*32+2k)/(h*32+2k+1) <- u16x2 exp_q for those 4 channels
    __shared__ uint32_t buf[64 * PX];
    __shared__ float slut[256];
    __shared__ int smax[NTHREADS];
    __shared__ float ssum[NTHREADS];

    int tid = threadIdx.x;
    slut[tid] = g_exp_lut[tid];
    slut[tid + 128] = g_exp_lut[tid + 128];

    int h = tid >> 6;                  // half: channels [h*64, h*64+64)
    int px = tid & 63;                 // pixel within tile

    int tile = blockIdx.x;             // b * 100 + t
    int b = tile / (HW_DIM / PX);
    int hw = (tile % (HW_DIM / PX)) * PX + px;

    const int* p = in + (size_t)b * C_DIM * HW_DIM + (size_t)(h * 64) * HW_DIM + hw;

    // ---- pass 1: load own 64 channels, byte-pack, partial max ----
    unsigned mx4 = 0x80808080u;        // all lanes = -128
#pragma unroll
    for (int k = 0; k < KITER; k++) {
        int q0 = __ldcs(&p[(4 * k + 0) * HW_DIM]);
        int q1 = __ldcs(&p[(4 * k + 1) * HW_DIM]);
        int q2 = __ldcs(&p[(4 * k + 2) * HW_DIM]);
        int q3 = __ldcs(&p[(4 * k + 3) * HW_DIM]);
        unsigned w = (unsigned)(q0 & 0xFF) | ((unsigned)(q1 & 0xFF) << 8) |
                     ((unsigned)(q2 & 0xFF) << 16) | ((unsigned)q3 << 24);
        mx4 = __vmaxs4(mx4, w);
        buf[(h * 32 + 2 * k) * PX + px] = w;
    }
    int mp = (int)(signed char)(mx4 & 0xFF);
    mp = max(mp, (int)(signed char)((mx4 >> 8) & 0xFF));
    mp = max(mp, (int)(signed char)((mx4 >> 16) & 0xFF));
    mp = max(mp, (int)(signed char)(mx4 >> 24));
    smax[tid] = mp;
    __syncthreads();
    int m = max(smax[px], smax[px + 64]);

    // ---- pass 2: exp LUT (one lookup/elem), partial sum, overwrite in place ----
    float sum = 0.0f;
#pragma unroll
    for (int k = 0; k < KITER; k++) {
        unsigned w = buf[(h * 32 + 2 * k) * PX + px];
        int d0 = m - (int)(signed char)(w & 0xFF);
        int d1 = m - (int)(signed char)((w >> 8) & 0xFF);
        int d2 = m - (int)(signed char)((w >> 16) & 0xFF);
        int d3 = m - (int)(signed char)(w >> 24);
        float e0 = slut[d0], e1 = slut[d1], e2 = slut[d2], e3 = slut[d3];
        sum += (e0 + e1) + (e2 + e3);  // integers < 2^22: exact
        buf[(h * 32 + 2 * k + 0) * PX + px] = (uint32_t)(int)e0 | (((uint32_t)(int)e1) << 16);
        buf[(h * 32 + 2 * k + 1) * PX + px] = (uint32_t)(int)e2 | (((uint32_t)(int)e3) << 16);
    }
    ssum[tid] = sum;
    __syncthreads();
    sum = ssum[px] + ssum[px + 64];    // both integer-valued, exact

    // ---- reciprocal (both half-threads compute identically) ----
    // shift = ceil(log2(128)) = 7
    float sum_sh = rintf(sum * 0.0078125f);                 // exact /128
    sum_sh = fminf(fmaxf(sum_sh, -32768.0f), 32767.0f);
    const float DIVSC = (float)(2.0 / 65535.0 * 128.0);
    float v = __fmul_rn(sum_sh, DIVSC);
    const float RSCALE = (float)((1.0 / 0.1) * 2.0 / 65535.0);

    float r = quant_i16(__fdiv_rn(1.0f, 0.001f), RSCALE);   // left const
    if (v >= 0.001f) {                                      // line (0.001,0.1)
        float y0 = __fdiv_rn(1.0f, 0.001f), y1 = __fdiv_rn(1.0f, 0.1f);
        float t = __fadd_rn(y0, __fmul_rn(__fadd_rn(v, -0.001f),
                                          __fdiv_rn(__fadd_rn(y1, -y0), (float)(0.1 - 0.001))));
        r = quant_i16(t, RSCALE);
    }
    if (v >= 0.1f) {                                        // table (0.1,250)
        float idxf = rintf(__fmul_rn(__fadd_rn(v, -0.1f), (float)(255.0 / 249.9)));
        idxf = fminf(fmaxf(idxf, 0.0f), 255.0f);
        r = g_rtab1[(int)idxf];
    }
    if (v >= 250.0f) {                                      // table (250,500)
        float idxf = rintf(__fmul_rn(__fadd_rn(v, -250.0f), (float)(255.0 / 250.0)));
        idxf = fminf(fmaxf(idxf, 0.0f), 255.0f);
        r = g_rtab2[(int)idxf];
    }
    if (v >= 500.0f) {                                      // line (500,700)
        float y0 = __fdiv_rn(1.0f, 500.0f), y1 = __fdiv_rn(1.0f, 700.0f);
        float t = __fadd_rn(y0, __fmul_rn(__fadd_rn(v, -500.0f),
                                          __fdiv_rn(__fadd_rn(y1, -y0), 200.0f)));
        r = quant_i16(t, RSCALE);
    }
    if (v > 700.0f) r = quant_i16(__fdiv_rn(1.0f, 700.0f), RSCALE);

    // ---- pass 3: out = clip(round((exp_q*recip_q)*K), i8) * OUT_SCALE ----
    const float KF = (float)((2.0 / 65535.0) * ((1.0 / 0.1) * 2.0 / 65535.0) / (2.0 / 255.0));
    const float OUTSC = (float)(2.0 / 255.0);
    float* po = out + (size_t)b * C_DIM * HW_DIM + (size_t)(h * 64) * HW_DIM + hw;
#pragma unroll
    for (int k = 0; k < KITER; k++) {
        unsigned w0 = buf[(h * 32 + 2 * k + 0) * PX + px];
        unsigned w1 = buf[(h * 32 + 2 * k + 1) * PX + px];
        float e0 = (float)(w0 & 0xFFFF);
        float e1 = (float)(w0 >> 16);
        float e2 = (float)(w1 & 0xFFFF);
        float e3 = (float)(w1 >> 16);
        float p0 = rintf(__fmul_rn(__fmul_rn(e0, r), KF));
        float p1 = rintf(__fmul_rn(__fmul_rn(e1, r), KF));
        float p2 = rintf(__fmul_rn(__fmul_rn(e2, r), KF));
        float p3 = rintf(__fmul_rn(__fmul_rn(e3, r), KF));
        p0 = fminf(fmaxf(p0, -128.0f), 127.0f);
        p1 = fminf(fmaxf(p1, -128.0f), 127.0f);
        p2 = fminf(fmaxf(p2, -128.0f), 127.0f);
        p3 = fminf(fmaxf(p3, -128.0f), 127.0f);
        __stcs(&po[(4 * k + 0) * HW_DIM], p0 * OUTSC);
        __stcs(&po[(4 * k + 1) * HW_DIM], p1 * OUTSC);
        __stcs(&po[(4 * k + 2) * HW_DIM], p2 * OUTSC);
        __stcs(&po[(4 * k + 3) * HW_DIM], p3 * OUTSC);
    }
}

extern "C" void kernel_launch(void* const* d_in, const int* in_sizes, int n_in,
                              void* d_out, int out_size) {
    const int* data = (const int*)d_in[0];
    const float* data_scale = (const float*)d_in[1];
    float* out = (float*)d_out;

    build_luts_kernel<<<1, 256>>>(data_scale);

    int total = in_sizes[0];
    int B = total / (C_DIM * HW_DIM);
    int blocks = B * (HW_DIM / PX);
    quant_softmax_kernel<<<blocks, NTHREADS>>>(data, out);
}

// round 6
// speedup vs baseline: 1.4657x; 1.0043x over previous
#include <cuda_runtime.h>
#include <math.h>
#include <stdint.h>

// ---------------------------------------------------------------------------
// QuantSoftmax: B=32, C=128, H=W=80 (HW=6400). int32 input (int8 repr, zp=0),
// float32 output. Piecewise-quantized exp (qint16) + reciprocal (qint16),
// requantized to int8*OUT_SCALE.
//
// xd = -(qmax - q)*ds takes only 256 values -> exp collapses to a 256-entry
// LUT built once per launch. Main kernel: warp = 8 pixels x 4 channel-
// quarters; each thread owns 32 channels of one pixel entirely in registers
// (byte-packed q, u16-packed exp_q). Max/sum reduced via shfl_xor — no smem
// staging, no syncthreads in the hot path. Exp LUT replicated 16x in smem to
// cut random-index bank conflicts.
// ---------------------------------------------------------------------------

#define C_DIM 128
#define HW_DIM 6400
#define NTHREADS 256   // 8 warps -> 64 pixels per CTA
#define PX_PER_CTA 64

__device__ float g_exp_lut[256];   // quantized exp value (integer-valued float)
__device__ float g_rtab1[256];     // recip table, region (0.1, 250)
__device__ float g_rtab2[256];     // recip table, region (250, 500)

__device__ __forceinline__ float quant_i16(float y, float scale) {
    float q = rintf(__fdiv_rn(y, scale));           // jnp.round = half-even
    return fminf(fmaxf(q, -32768.0f), 32767.0f);
}

__device__ __forceinline__ float exp_f32(float x) {
    return (float)exp((double)x);                   // ~correctly-rounded f32 exp
}

// one block, 256 threads: build LUTs
__global__ void build_luts_kernel(const float* __restrict__ ds_ptr) {
    int i = threadIdx.x;                            // 0..255
    float ds = ds_ptr[0];
    const float ESCALE = (float)(2.0 / 65535.0);
    const float RSCALE = (float)((1.0 / 0.1) * 2.0 / 65535.0);

    // ---- exp LUT over d = qmax - q in [0,255], x = -d*ds ----
    float x = __fmul_rn(-(float)i, ds);
    float y = quant_i16(exp_f32(-40.0f), ESCALE);   // left constant
    if (x >= -40.0f) {                              // line (-40,-20)
        float y0 = exp_f32(-40.0f), y1 = exp_f32(-20.0f);
        float t = __fadd_rn(y0, __fmul_rn(__fadd_rn(x, 40.0f),
                                          __fdiv_rn(__fadd_rn(y1, -y0), 20.0f)));
        y = quant_i16(t, ESCALE);
    }
    if (x >= -20.0f) {                              // table (-20,-10)
        float idxf = rintf(__fmul_rn(__fadd_rn(x, 20.0f), (float)(255.0 / 10.0)));
        idxf = fminf(fmaxf(idxf, 0.0f), 255.0f);
        float step = __fdiv_rn(10.0f, 255.0f);
        float xs = __fadd_rn(-20.0f, __fmul_rn(idxf, step));
        y = quant_i16(exp_f32(xs), ESCALE);
    }
    if (x >= -10.0f) {                              // table (-10,0)
        float idxf = rintf(__fmul_rn(__fadd_rn(x, 10.0f), (float)(255.0 / 10.0)));
        idxf = fminf(fmaxf(idxf, 0.0f), 255.0f);
        float step = __fdiv_rn(10.0f, 255.0f);
        float xs = __fadd_rn(-10.0f, __fmul_rn(idxf, step));
        y = quant_i16(exp_f32(xs), ESCALE);
    }
    if (x >= 0.0f) {                                // line (0,1): only d=0
        float y0 = exp_f32(0.0f), y1 = exp_f32(1.0f);
        float t = __fadd_rn(y0, __fmul_rn(x, __fdiv_rn(__fadd_rn(y1, -y0), 1.0f)));
        y = quant_i16(t, ESCALE);
    }
    if (x > 1.0f) y = quant_i16(exp_f32(1.0f), ESCALE);
    g_exp_lut[i] = y;

    // ---- recip tables (independent of ds) ----
    {
        float step1 = __fdiv_rn((float)(250.0 - 0.1), 255.0f);
        float xs1 = __fadd_rn(0.1f, __fmul_rn((float)i, step1));
        g_rtab1[i] = quant_i16(__fdiv_rn(1.0f, xs1), RSCALE);
        float step2 = __fdiv_rn(250.0f, 255.0f);
        float xs2 = __fadd_rn(250.0f, __fmul_rn((float)i, step2));
        g_rtab2[i] = quant_i16(__fdiv_rn(1.0f, xs2), RSCALE);
    }
}

__global__ __launch_bounds__(NTHREADS, 5)
void quant_softmax_kernel(const int* __restrict__ in, float* __restrict__ out) {
    // 16x replicated exp LUT: slutR[d*16 + (lane&15)], 16 KB
    __shared__ float slutR[256 * 16];

    int tid = threadIdx.x;
#pragma unroll
    for (int i = 0; i < 16; i++) {
        int j = tid + i * NTHREADS;          // 0..4095, consecutive -> conflict-free
        slutR[j] = g_exp_lut[j >> 4];
    }
    __syncthreads();

    int lane = tid & 31;
    int warp = tid >> 5;
    int pxi = lane & 7;                      // pixel within warp's 8
    int cq = lane >> 3;                      // channel quarter 0..3
    int rep = lane & 15;                     // LUT replica

    int P = blockIdx.x * PX_PER_CTA + warp * 8 + pxi;   // global pixel
    int b = P / HW_DIM;                      // CTA never straddles b (6400 = 100*64)
    int hw = P - b * HW_DIM;

    const int* p = in + (size_t)b * C_DIM * HW_DIM + (size_t)(cq * 32) * HW_DIM + hw;

    // ---- pass 1: load own 32 channels into 8 byte-packed regs, partial max ----
    unsigned w[8];
    unsigned mx4 = 0x80808080u;              // all lanes = -128
#pragma unroll
    for (int k = 0; k < 8; k++) {
        int q0 = __ldcs(&p[(4 * k + 0) * HW_DIM]);
        int q1 = __ldcs(&p[(4 * k + 1) * HW_DIM]);
        int q2 = __ldcs(&p[(4 * k + 2) * HW_DIM]);
        int q3 = __ldcs(&p[(4 * k + 3) * HW_DIM]);
        unsigned t = (unsigned)(q0 & 0xFF) | ((unsigned)(q1 & 0xFF) << 8) |
                     ((unsigned)(q2 & 0xFF) << 16) | ((unsigned)q3 << 24);
        mx4 = __vmaxs4(mx4, t);
        w[k] = t;
    }
    int m = (int)(signed char)(mx4 & 0xFF);
    m = max(m, (int)(signed char)((mx4 >> 8) & 0xFF));
    m = max(m, (int)(signed char)((mx4 >> 16) & 0xFF));
    m = max(m, (int)(signed char)(mx4 >> 24));
    // combine across the 4 channel-quarter threads of this pixel (lanes ^8, ^16)
    m = max(m, __shfl_xor_sync(0xFFFFFFFFu, m, 8));
    m = max(m, __shfl_xor_sync(0xFFFFFFFFu, m, 16));

    // ---- pass 2: exp LUT (one lookup/elem), keep exp_q u16-packed in regs ----
    unsigned ew[16];
    float sum = 0.0f;
#pragma unroll
    for (int k = 0; k < 8; k++) {
        unsigned t = w[k];
        int d0 = m - (int)(signed char)(t & 0xFF);
        int d1 = m - (int)(signed char)((t >> 8) & 0xFF);
        int d2 = m - (int)(signed char)((t >> 16) & 0xFF);
        int d3 = m - (int)(signed char)(t >> 24);
        float e0 = slutR[d0 * 16 + rep];
        float e1 = slutR[d1 * 16 + rep];
        float e2 = slutR[d2 * 16 + rep];
        float e3 = slutR[d3 * 16 + rep];
        sum += (e0 + e1) + (e2 + e3);        // integers: total < 2^23, exact
        ew[2 * k + 0] = (unsigned)(int)e0 | (((unsigned)(int)e1) << 16);
        ew[2 * k + 1] = (unsigned)(int)e2 | (((unsigned)(int)e3) << 16);
    }
    sum += __shfl_xor_sync(0xFFFFFFFFu, sum, 8);
    sum += __shfl_xor_sync(0xFFFFFFFFu, sum, 16);

    // ---- reciprocal (all 4 quarter-threads compute identically) ----
    // shift = ceil(log2(128)) = 7
    float sum_sh = rintf(sum * 0.0078125f);                 // exact /128
    sum_sh = fminf(fmaxf(sum_sh, -32768.0f), 32767.0f);
    const float DIVSC = (float)(2.0 / 65535.0 * 128.0);
    float v = __fmul_rn(sum_sh, DIVSC);
    const float RSCALE = (float)((1.0 / 0.1) * 2.0 / 65535.0);

    float r = quant_i16(__fdiv_rn(1.0f, 0.001f), RSCALE);   // left const
    if (v >= 0.001f) {                                      // line (0.001,0.1)
        float y0 = __fdiv_rn(1.0f, 0.001f), y1 = __fdiv_rn(1.0f, 0.1f);
        float t = __fadd_rn(y0, __fmul_rn(__fadd_rn(v, -0.001f),
                                          __fdiv_rn(__fadd_rn(y1, -y0), (float)(0.1 - 0.001))));
        r = quant_i16(t, RSCALE);
    }
    if (v >= 0.1f) {                                        // table (0.1,250)
        float idxf = rintf(__fmul_rn(__fadd_rn(v, -0.1f), (float)(255.0 / 249.9)));
        idxf = fminf(fmaxf(idxf, 0.0f), 255.0f);
        r = g_rtab1[(int)idxf];
    }
    if (v >= 250.0f) {                                      // table (250,500)
        float idxf = rintf(__fmul_rn(__fadd_rn(v, -250.0f), (float)(255.0 / 250.0)));
        idxf = fminf(fmaxf(idxf, 0.0f), 255.0f);
        r = g_rtab2[(int)idxf];
    }
    if (v >= 500.0f) {                                      // line (500,700)
        float y0 = __fdiv_rn(1.0f, 500.0f), y1 = __fdiv_rn(1.0f, 700.0f);
        float t = __fadd_rn(y0, __fmul_rn(__fadd_rn(v, -500.0f),
                                          __fdiv_rn(__fadd_rn(y1, -y0), 200.0f)));
        r = quant_i16(t, RSCALE);
    }
    if (v > 700.0f) r = quant_i16(__fdiv_rn(1.0f, 700.0f), RSCALE);

    // ---- pass 3: out = clip(round((exp_q*recip_q)*K), i8) * OUT_SCALE ----
    const float KF = (float)((2.0 / 65535.0) * ((1.0 / 0.1) * 2.0 / 65535.0) / (2.0 / 255.0));
    const float OUTSC = (float)(2.0 / 255.0);
    float* po = out + (size_t)b * C_DIM * HW_DIM + (size_t)(cq * 32) * HW_DIM + hw;
#pragma unroll
    for (int k = 0; k < 8; k++) {
        unsigned w0 = ew[2 * k + 0];
        unsigned w1 = ew[2 * k + 1];
        float e0 = (float)(w0 & 0xFFFF);
        float e1 = (float)(w0 >> 16);
        float e2 = (float)(w1 & 0xFFFF);
        float e3 = (float)(w1 >> 16);
        float p0 = rintf(__fmul_rn(__fmul_rn(e0, r), KF));
        float p1 = rintf(__fmul_rn(__fmul_rn(e1, r), KF));
        float p2 = rintf(__fmul_rn(__fmul_rn(e2, r), KF));
        float p3 = rintf(__fmul_rn(__fmul_rn(e3, r), KF));
        p0 = fminf(fmaxf(p0, -128.0f), 127.0f);
        p1 = fminf(fmaxf(p1, -128.0f), 127.0f);
        p2 = fminf(fmaxf(p2, -128.0f), 127.0f);
        p3 = fminf(fmaxf(p3, -128.0f), 127.0f);
        __stcs(&po[(4 * k + 0) * HW_DIM], p0 * OUTSC);
        __stcs(&po[(4 * k + 1) * HW_DIM], p1 * OUTSC);
        __stcs(&po[(4 * k + 2) * HW_DIM], p2 * OUTSC);
        __stcs(&po[(4 * k + 3) * HW_DIM], p3 * OUTSC);
    }
}

extern "C" void kernel_launch(void* const* d_in, const int* in_sizes, int n_in,
                              void* d_out, int out_size) {
    const int* data = (const int*)d_in[0];
    const float* data_scale = (const float*)d_in[1];
    float* out = (float*)d_out;

    build_luts_kernel<<<1, 256>>>(data_scale);

    int total = in_sizes[0];
    int B = total / (C_DIM * HW_DIM);
    int blocks = (B * HW_DIM) / PX_PER_CTA;
    quant_softmax_kernel<<<blocks, NTHREADS>>>(data, out);
}